// round 11
// baseline (speedup 1.0000x reference)
#include <cuda_runtime.h>
#include <math.h>

// Problem constants (fixed by the reference)
#define NATOMS     8192
#define MAX_PAIRS  (64 * 8192)     // 524288
#define CUT2       25.0f           // cutoff_upper^2; cutoff_lower = 0
#define NCELL1     9               // 45.0 / 5.0
#define NCELLS     (NCELL1 * NCELL1 * NCELL1)   // 729
#define CAP        48              // bucket capacity (Poisson mean 11.2)
#define MASK_WORDS 256             // 8192 bits per row
#define NBLK       256             // pairs grid: 32 rows (warps) per block
#define NTHR       1024
#define ROWS       32
#define FULLMASK   0xffffffffu

// Scratch (device globals; zero at module load). Invariants per replay:
//   g_cell_cnt: zeroed by pairs_kernel tail phase of the PREVIOUS run
//   g_state:    zeroed by build_kernel of the CURRENT run (before pairs)
__device__ int      g_cell_cnt[NCELLS];
__device__ float4   g_bpos[NCELLS * CAP];    // (x, y, z, atom_idx bits)
__device__ int      g_bbatch[NCELLS * CAP];
__device__ unsigned g_state[NBLK];           // decoupled-lookback state

// d2 with the SAME rounding as the reference: rounded products, then ((a+b)+c).
__device__ __forceinline__ float d2_exact(float dx, float dy, float dz) {
    float a = __fmul_rn(dx, dx);
    float b = __fmul_rn(dy, dy);
    float c = __fmul_rn(dz, dz);
    return __fadd_rn(__fadd_rn(a, b), c);
}

__device__ __forceinline__ int cell_coord(float p) {
    int c = (int)(p * 0.2f);
    return c < 0 ? 0 : (c > NCELL1 - 1 ? NCELL1 - 1 : c);
}

// ---------------------------------------------------------------------------
// K1: bucketed cell-list build + g_state reset (stream-ordered before pairs).
// ---------------------------------------------------------------------------
__global__ void build_kernel(const float* __restrict__ pos,
                             const int*   __restrict__ batch) {
    const int i = blockIdx.x * blockDim.x + threadIdx.x;
    if (i < NBLK) g_state[i] = 0u;           // reset lookback state
    if (i >= NATOMS) return;
    const float x = pos[3 * i + 0];
    const float y = pos[3 * i + 1];
    const float z = pos[3 * i + 2];
    const int c = cell_coord(x) * 81 + cell_coord(y) * 9 + cell_coord(z);
    const int slot = atomicAdd(&g_cell_cnt[c], 1);
    if (slot < CAP) {
        g_bpos[c * CAP + slot]   = make_float4(x, y, z, __int_as_float(i));
        g_bbatch[c * CAP + slot] = batch[i];
    }
}

// ---------------------------------------------------------------------------
// K2: fused count + scan (decoupled lookback) + ordered write + tail fill.
// 256 blocks x 1024 threads, launch_bounds(1024,2): 2 blocks/SM x 148 = 296
// >= 256, so ALL blocks are co-resident -> forward-polling g_state[255] is
// deadlock-free. flag=2 at block 255 implies (by lookback induction) every
// block finished its eval phase, so the tail fill and g_cell_cnt restore
// cannot race any reader.
// One warp per row; flattened neighbor-cell candidate space with warp-scan
// table + bisection. Row bitmask in shared gives exact row-major order.
// ---------------------------------------------------------------------------
__global__ void __launch_bounds__(NTHR, 2)
pairs_kernel(const float* __restrict__ pos,
             const int*   __restrict__ batch,
             float*       __restrict__ out) {
    __shared__ unsigned smask[ROWS][MASK_WORDS];   // 32 KB
    __shared__ int scum[ROWS][32];                 // per-warp cell cum table
    __shared__ int sbase[ROWS][32];                // per-warp (cell*CAP - cum)
    __shared__ int scnt[ROWS];
    __shared__ int srowoff[ROWS];
    __shared__ int stotal;
    const int warp = threadIdx.x >> 5;
    const int lane = threadIdx.x & 31;
    const int b = blockIdx.x;
    const int i = b * ROWS + warp;

    #pragma unroll
    for (int k = lane; k < MASK_WORDS; k += 32) smask[warp][k] = 0;

    const float pix = pos[3 * i + 0];
    const float piy = pos[3 * i + 1];
    const float piz = pos[3 * i + 2];
    const int   bi  = batch[i];
    __syncwarp();

    const int cx = cell_coord(pix), cy = cell_coord(piy), cz = cell_coord(piz);
    const int x0 = max(cx - 1, 0), x1 = min(cx + 1, NCELL1 - 1);
    const int y0 = max(cy - 1, 0), y1 = min(cy + 1, NCELL1 - 1);
    const int z0 = max(cz - 1, 0), z1 = min(cz + 1, NCELL1 - 1);
    const int nyc = y1 - y0 + 1;
    const int nzc = z1 - z0 + 1;
    const int nyz = nyc * nzc;
    const int ncells = (x1 - x0 + 1) * nyz;

    // ---- flattened cell table (one lane per neighbor cell) ----
    int cnt_l = 0, base_l = 0;
    if (lane < ncells) {
        const int lx  = lane / nyz;
        const int rem = lane - lx * nyz;
        const int ly  = rem / nzc;
        const int lz  = rem - ly * nzc;
        const int cell = (x0 + lx) * 81 + (y0 + ly) * 9 + (z0 + lz);
        int c = g_cell_cnt[cell];
        cnt_l  = c > CAP ? CAP : c;
        base_l = cell * CAP;
    }
    int incl = cnt_l;
    #pragma unroll
    for (int d = 1; d < 32; d <<= 1) {
        const int u = __shfl_up_sync(FULLMASK, incl, d);
        if (lane >= d) incl += u;
    }
    scum[warp][lane]  = incl - cnt_l;            // lanes >= ncells hold tot
    sbase[warp][lane] = base_l - (incl - cnt_l); // slot = sbase[k] + s
    const int tot = __shfl_sync(FULLMASK, incl, 31);
    __syncwarp();

    unsigned* __restrict__ mask = smask[warp];
    const int* __restrict__ cum = scum[warp];
    const int* __restrict__ sb  = sbase[warp];

    // ---- flat candidate loop: bisect cum table (largest k: cum[k] <= s) ----
    for (int s = lane; s < tot; s += 32) {
        int k = 0;
        if (cum[k + 16] <= s) k += 16;
        if (cum[k + 8]  <= s) k += 8;
        if (cum[k + 4]  <= s) k += 4;
        if (cum[k + 2]  <= s) k += 2;
        if (cum[k + 1]  <= s) k += 1;
        const int slot = sb[k] + s;
        const float4 pj = g_bpos[slot];
        const float dx = pix - pj.x;
        const float dy = piy - pj.y;
        const float dz = piz - pj.z;
        const float d2 = d2_exact(dx, dy, dz);
        const int j = __float_as_int(pj.w);
        if (d2 < CUT2 && j != i && g_bbatch[slot] == bi) {
            atomicOr(&mask[j >> 5], 1u << (j & 31));
        }
    }
    __syncwarp();

    // per-row count from the mask
    int cnt = 0;
    #pragma unroll
    for (int k = 0; k < 8; k++) cnt += __popc(mask[lane * 8 + k]);
    cnt = __reduce_add_sync(FULLMASK, cnt);
    if (lane == 0) scnt[warp] = cnt;
    __syncthreads();

    // warp 0: publish aggregate, decoupled lookback, publish inclusive prefix
    if (warp == 0) {
        const int myc = scnt[lane];              // lane l owns row b*32+l
        int inc2 = myc;
        #pragma unroll
        for (int d = 1; d < 32; d <<= 1) {
            const int u = __shfl_up_sync(FULLMASK, inc2, d);
            if (lane >= d) inc2 += u;
        }
        const int agg = __shfl_sync(FULLMASK, inc2, 31);
        if (lane == 0) atomicExch(&g_state[b], (1u << 30) | (unsigned)agg);

        int excl = 0;
        int look = b - 1;
        bool done = (look < 0);
        while (!done) {
            const int idx = look - lane;
            unsigned v;
            if (idx >= 0) {
                do { v = *(volatile unsigned*)&g_state[idx]; } while (v == 0u);
            } else {
                v = (2u << 30);               // virtual PREFIX=0 before block 0
            }
            const unsigned flag = v >> 30;
            const int val = (int)(v & 0x3FFFFFFFu);
            const unsigned pmask = __ballot_sync(FULLMASK, flag == 2u);
            const int limit = (pmask != 0u) ? (__ffs(pmask) - 1) : 31;
            int contrib = (lane <= limit) ? val : 0;
            #pragma unroll
            for (int d = 16; d > 0; d >>= 1)
                contrib += __shfl_down_sync(FULLMASK, contrib, d);
            contrib = __shfl_sync(FULLMASK, contrib, 0);
            excl += contrib;
            if (pmask != 0u) done = true; else look -= 32;
        }
        if (lane == 0)
            atomicExch(&g_state[b], (2u << 30) | (unsigned)(excl + agg));
        srowoff[lane] = excl + inc2 - myc;       // global exclusive row offset
    }
    __syncthreads();

    // ---- ordered write: lane l owns words [8l,8l+8) -> j in [256l,256(l+1))
    int myc = 0;
    #pragma unroll
    for (int t = 0; t < 8; t++) myc += __popc(mask[lane * 8 + t]);

    int inclw = myc;
    #pragma unroll
    for (int d = 1; d < 32; d <<= 1) {
        const int u = __shfl_up_sync(FULLMASK, inclw, d);
        if (lane >= d) inclw += u;
    }
    int p = srowoff[warp] + inclw - myc;

    const float fi = (float)i;
    float* __restrict__ outI = out;
    float* __restrict__ outJ = out + MAX_PAIRS;
    float* __restrict__ outW = out + 2 * MAX_PAIRS;
    float* __restrict__ outV = out + 3 * MAX_PAIRS;

    #pragma unroll
    for (int t = 0; t < 8; t++) {
        unsigned word = mask[lane * 8 + t];      // re-read from shared (regs)
        const int jbase = (lane * 8 + t) * 32;
        while (word) {
            const int bpos = __ffs(word) - 1;
            word &= word - 1;
            const int j = jbase + bpos;
            const float dx = pix - pos[3 * j + 0];
            const float dy = piy - pos[3 * j + 1];
            const float dz = piz - pos[3 * j + 2];
            const float d2 = d2_exact(dx, dy, dz);
            if (p < MAX_PAIRS) {
                outI[p] = fi;
                outJ[p] = (float)j;
                outW[p] = sqrtf(d2);
                outV[3 * p + 0] = dx;
                outV[3 * p + 1] = dy;
                outV[3 * p + 2] = dz;
            }
            p++;
        }
    }

    // ---- tail phase: forward-poll the final prefix (safe: co-resident grid)
    if (threadIdx.x == 0) {
        unsigned v;
        do { v = *(volatile unsigned*)&g_state[NBLK - 1]; }
        while ((v >> 30) != 2u);
        stotal = (int)(v & 0x3FFFFFFFu);
    }
    __syncthreads();
    int total = stotal;
    if (total > MAX_PAIRS) total = MAX_PAIRS;

    // restore g_cell_cnt for the next replay (all evals finished by now)
    if (b == 0) {
        for (int k = threadIdx.x; k < NCELLS; k += NTHR) g_cell_cnt[k] = 0;
    }

    // fill invalid tail [total, MAX_PAIRS): index=-1, weight=0, vec=0
    for (int q = total + b * NTHR + threadIdx.x; q < MAX_PAIRS; q += NBLK * NTHR) {
        outI[q] = -1.0f;
        outJ[q] = -1.0f;
        outW[q] = 0.0f;
        outV[3 * q + 0] = 0.0f;
        outV[3 * q + 1] = 0.0f;
        outV[3 * q + 2] = 0.0f;
    }
}

// ---------------------------------------------------------------------------
extern "C" void kernel_launch(void* const* d_in, const int* in_sizes, int n_in,
                              void* d_out, int out_size) {
    const float* pos   = (const float*)d_in[0];   // [8192, 3] f32
    const int*   batch = (const int*)d_in[1];     // [8192] i32
    float* out = (float*)d_out;                   // 6 * MAX_PAIRS floats

    (void)in_sizes; (void)n_in; (void)out_size;

    build_kernel<<<NATOMS / 64, 64>>>(pos, batch);
    pairs_kernel<<<NBLK, NTHR>>>(pos, batch, out);
}

// round 12
// speedup vs baseline: 1.0022x; 1.0022x over previous
#include <cuda_runtime.h>
#include <math.h>

// Problem constants (fixed by the reference)
#define NATOMS     8192
#define MAX_PAIRS  (64 * 8192)     // 524288
#define CUT2       25.0f           // cutoff_upper^2; cutoff_lower = 0
#define NCELL1     9               // 45.0 / 5.0
#define NCELLS     (NCELL1 * NCELL1 * NCELL1)   // 729
#define CAP        48              // bucket capacity (Poisson mean 11.2)
#define MASK_WORDS 256             // 8192 bits per row
#define NBLK       256             // pairs grid: 32 rows (warps) per block
#define NTHR       1024
#define ROWS       32
#define FULLMASK   0xffffffffu

// Scratch (device globals; zero at module load). Invariants per replay:
//   g_cell_cnt: zeroed by pairs_kernel tail phase of the PREVIOUS run
//   g_state:    zeroed by build_kernel of the CURRENT run (before pairs)
__device__ int      g_cell_cnt[NCELLS];
__device__ float4   g_bpos[NCELLS * CAP];    // (x, y, z, atom_idx bits)
__device__ int      g_bbatch[NCELLS * CAP];
__device__ unsigned g_state[NBLK];           // decoupled-lookback state

// d2 with the SAME rounding as the reference: rounded products, then ((a+b)+c).
__device__ __forceinline__ float d2_exact(float dx, float dy, float dz) {
    float a = __fmul_rn(dx, dx);
    float b = __fmul_rn(dy, dy);
    float c = __fmul_rn(dz, dz);
    return __fadd_rn(__fadd_rn(a, b), c);
}

__device__ __forceinline__ int cell_coord(float p) {
    int c = (int)(p * 0.2f);
    return c < 0 ? 0 : (c > NCELL1 - 1 ? NCELL1 - 1 : c);
}

// ---------------------------------------------------------------------------
// K1: bucketed cell-list build + g_state reset (stream-ordered before pairs).
// ---------------------------------------------------------------------------
__global__ void build_kernel(const float* __restrict__ pos,
                             const int*   __restrict__ batch) {
    const int i = blockIdx.x * blockDim.x + threadIdx.x;
    if (i < NBLK) g_state[i] = 0u;           // reset lookback state
    if (i >= NATOMS) return;
    const float x = pos[3 * i + 0];
    const float y = pos[3 * i + 1];
    const float z = pos[3 * i + 2];
    const int c = cell_coord(x) * 81 + cell_coord(y) * 9 + cell_coord(z);
    const int slot = atomicAdd(&g_cell_cnt[c], 1);
    if (slot < CAP) {
        g_bpos[c * CAP + slot]   = make_float4(x, y, z, __int_as_float(i));
        g_bbatch[c * CAP + slot] = batch[i];
    }
}

// ---------------------------------------------------------------------------
// K2: fused count + scan (decoupled lookback) + ordered write + tail fill.
// 256 blocks x 1024 threads, launch_bounds(1024,2): all blocks co-resident
// (2/SM x 148 = 296 >= 256) so the forward poll on g_state[255] is
// deadlock-free, and its flag=2 implies every block finished its eval phase.
//
// NEW vs R11:
//  - cell-level culling: a lane's cell is dropped when the point-to-box
//    min distance already exceeds the cutoff (~30% fewer candidates)
//  - hit counting during eval (each (i,j) evaluated exactly once, so every
//    shared atomicOr sets a fresh bit) -> the 8-LDS mask count pass is gone
// ---------------------------------------------------------------------------
__global__ void __launch_bounds__(NTHR, 2)
pairs_kernel(const float* __restrict__ pos,
             const int*   __restrict__ batch,
             float*       __restrict__ out) {
    __shared__ unsigned smask[ROWS][MASK_WORDS];   // 32 KB
    __shared__ int scum[ROWS][32];                 // per-warp cell cum table
    __shared__ int sbase[ROWS][32];                // per-warp (cell*CAP - cum)
    __shared__ int scnt[ROWS];
    __shared__ int srowoff[ROWS];
    __shared__ int stotal;
    const int warp = threadIdx.x >> 5;
    const int lane = threadIdx.x & 31;
    const int b = blockIdx.x;
    const int i = b * ROWS + warp;

    #pragma unroll
    for (int k = lane; k < MASK_WORDS; k += 32) smask[warp][k] = 0;

    const float pix = pos[3 * i + 0];
    const float piy = pos[3 * i + 1];
    const float piz = pos[3 * i + 2];
    const int   bi  = batch[i];
    __syncwarp();

    const int cx = cell_coord(pix), cy = cell_coord(piy), cz = cell_coord(piz);
    const int x0 = max(cx - 1, 0), x1 = min(cx + 1, NCELL1 - 1);
    const int y0 = max(cy - 1, 0), y1 = min(cy + 1, NCELL1 - 1);
    const int z0 = max(cz - 1, 0), z1 = min(cz + 1, NCELL1 - 1);
    const int nyc = y1 - y0 + 1;
    const int nzc = z1 - z0 + 1;
    const int nyz = nyc * nzc;
    const int ncells = (x1 - x0 + 1) * nyz;

    // ---- flattened cell table (one lane per neighbor cell) + box culling ---
    int cnt_l = 0, base_l = 0;
    if (lane < ncells) {
        const int lx  = lane / nyz;
        const int rem = lane - lx * nyz;
        const int ly  = rem / nzc;
        const int lz  = rem - ly * nzc;
        const int X = x0 + lx, Y = y0 + ly, Z = z0 + lz;
        // point-to-box min distance (conservative: 1e-3 slack for rounding)
        const float lox = 5.0f * X, hix = lox + 5.0f;
        const float loy = 5.0f * Y, hiy = loy + 5.0f;
        const float loz = 5.0f * Z, hiz = loz + 5.0f;
        const float ddx = fmaxf(fmaxf(lox - pix, pix - hix), 0.0f);
        const float ddy = fmaxf(fmaxf(loy - piy, piy - hiy), 0.0f);
        const float ddz = fmaxf(fmaxf(loz - piz, piz - hiz), 0.0f);
        const float d2min = ddx * ddx + ddy * ddy + ddz * ddz;
        const int cell = X * 81 + Y * 9 + Z;
        if (d2min < CUT2 + 1e-3f) {
            int c = g_cell_cnt[cell];
            cnt_l = c > CAP ? CAP : c;
        }
        base_l = cell * CAP;
    }
    int incl = cnt_l;
    #pragma unroll
    for (int d = 1; d < 32; d <<= 1) {
        const int u = __shfl_up_sync(FULLMASK, incl, d);
        if (lane >= d) incl += u;
    }
    scum[warp][lane]  = incl - cnt_l;            // lanes >= ncells hold tot
    sbase[warp][lane] = base_l - (incl - cnt_l); // slot = sbase[k] + s
    const int tot = __shfl_sync(FULLMASK, incl, 31);
    __syncwarp();

    unsigned* __restrict__ mask = smask[warp];
    const int* __restrict__ cum = scum[warp];
    const int* __restrict__ sb  = sbase[warp];

    // ---- flat candidate loop: bisect cum table; count hits inline ----
    int hits = 0;
    for (int s = lane; s < tot; s += 32) {
        int k = 0;
        if (cum[k + 16] <= s) k += 16;
        if (cum[k + 8]  <= s) k += 8;
        if (cum[k + 4]  <= s) k += 4;
        if (cum[k + 2]  <= s) k += 2;
        if (cum[k + 1]  <= s) k += 1;
        const int slot = sb[k] + s;
        const float4 pj = g_bpos[slot];
        const float dx = pix - pj.x;
        const float dy = piy - pj.y;
        const float dz = piz - pj.z;
        const float d2 = d2_exact(dx, dy, dz);
        const int j = __float_as_int(pj.w);
        if (d2 < CUT2 && j != i && g_bbatch[slot] == bi) {
            atomicOr(&mask[j >> 5], 1u << (j & 31));
            hits++;
        }
    }
    // per-row count = total hits (each (i,j) evaluated exactly once)
    const int cnt = __reduce_add_sync(FULLMASK, hits);
    if (lane == 0) scnt[warp] = cnt;
    __syncthreads();

    // warp 0: publish aggregate, decoupled lookback, publish inclusive prefix
    if (warp == 0) {
        const int myc = scnt[lane];              // lane l owns row b*32+l
        int inc2 = myc;
        #pragma unroll
        for (int d = 1; d < 32; d <<= 1) {
            const int u = __shfl_up_sync(FULLMASK, inc2, d);
            if (lane >= d) inc2 += u;
        }
        const int agg = __shfl_sync(FULLMASK, inc2, 31);
        if (lane == 0) atomicExch(&g_state[b], (1u << 30) | (unsigned)agg);

        int excl = 0;
        int look = b - 1;
        bool done = (look < 0);
        while (!done) {
            const int idx = look - lane;
            unsigned v;
            if (idx >= 0) {
                do { v = *(volatile unsigned*)&g_state[idx]; } while (v == 0u);
            } else {
                v = (2u << 30);               // virtual PREFIX=0 before block 0
            }
            const unsigned flag = v >> 30;
            const int val = (int)(v & 0x3FFFFFFFu);
            const unsigned pmask = __ballot_sync(FULLMASK, flag == 2u);
            const int limit = (pmask != 0u) ? (__ffs(pmask) - 1) : 31;
            int contrib = (lane <= limit) ? val : 0;
            #pragma unroll
            for (int d = 16; d > 0; d >>= 1)
                contrib += __shfl_down_sync(FULLMASK, contrib, d);
            contrib = __shfl_sync(FULLMASK, contrib, 0);
            excl += contrib;
            if (pmask != 0u) done = true; else look -= 32;
        }
        if (lane == 0)
            atomicExch(&g_state[b], (2u << 30) | (unsigned)(excl + agg));
        srowoff[lane] = excl + inc2 - myc;       // global exclusive row offset
    }
    __syncthreads();

    // ---- ordered write: lane l owns words [8l,8l+8) -> j in [256l,256(l+1))
    int myc = 0;
    #pragma unroll
    for (int t = 0; t < 8; t++) myc += __popc(mask[lane * 8 + t]);

    int inclw = myc;
    #pragma unroll
    for (int d = 1; d < 32; d <<= 1) {
        const int u = __shfl_up_sync(FULLMASK, inclw, d);
        if (lane >= d) inclw += u;
    }
    int p = srowoff[warp] + inclw - myc;

    const float fi = (float)i;
    float* __restrict__ outI = out;
    float* __restrict__ outJ = out + MAX_PAIRS;
    float* __restrict__ outW = out + 2 * MAX_PAIRS;
    float* __restrict__ outV = out + 3 * MAX_PAIRS;

    #pragma unroll
    for (int t = 0; t < 8; t++) {
        unsigned word = mask[lane * 8 + t];
        const int jbase = (lane * 8 + t) * 32;
        while (word) {
            const int bpos = __ffs(word) - 1;
            word &= word - 1;
            const int j = jbase + bpos;
            const float dx = pix - pos[3 * j + 0];
            const float dy = piy - pos[3 * j + 1];
            const float dz = piz - pos[3 * j + 2];
            const float d2 = d2_exact(dx, dy, dz);
            if (p < MAX_PAIRS) {
                outI[p] = fi;
                outJ[p] = (float)j;
                outW[p] = sqrtf(d2);
                outV[3 * p + 0] = dx;
                outV[3 * p + 1] = dy;
                outV[3 * p + 2] = dz;
            }
            p++;
        }
    }

    // ---- tail phase: forward-poll the final prefix (safe: co-resident grid)
    if (threadIdx.x == 0) {
        unsigned v;
        do { v = *(volatile unsigned*)&g_state[NBLK - 1]; }
        while ((v >> 30) != 2u);
        stotal = (int)(v & 0x3FFFFFFFu);
    }
    __syncthreads();
    int total = stotal;
    if (total > MAX_PAIRS) total = MAX_PAIRS;

    // restore g_cell_cnt for the next replay (all evals finished by now)
    if (b == 0) {
        for (int k = threadIdx.x; k < NCELLS; k += NTHR) g_cell_cnt[k] = 0;
    }

    // fill invalid tail [total, MAX_PAIRS): index=-1, weight=0, vec=0
    for (int q = total + b * NTHR + threadIdx.x; q < MAX_PAIRS; q += NBLK * NTHR) {
        outI[q] = -1.0f;
        outJ[q] = -1.0f;
        outW[q] = 0.0f;
        outV[3 * q + 0] = 0.0f;
        outV[3 * q + 1] = 0.0f;
        outV[3 * q + 2] = 0.0f;
    }
}

// ---------------------------------------------------------------------------
extern "C" void kernel_launch(void* const* d_in, const int* in_sizes, int n_in,
                              void* d_out, int out_size) {
    const float* pos   = (const float*)d_in[0];   // [8192, 3] f32
    const int*   batch = (const int*)d_in[1];     // [8192] i32
    float* out = (float*)d_out;                   // 6 * MAX_PAIRS floats

    (void)in_sizes; (void)n_in; (void)out_size;

    build_kernel<<<NATOMS / 64, 64>>>(pos, batch);
    pairs_kernel<<<NBLK, NTHR>>>(pos, batch, out);
}

// round 13
// speedup vs baseline: 1.0268x; 1.0245x over previous
#include <cuda_runtime.h>
#include <math.h>

// Problem constants (fixed by the reference)
#define NATOMS     8192
#define MAX_PAIRS  (64 * 8192)     // 524288
#define CUT2       25.0f           // cutoff_upper^2; cutoff_lower = 0
#define NCELL1     9               // 45.0 / 5.0
#define NCELLS     (NCELL1 * NCELL1 * NCELL1)   // 729
#define CAP        48              // bucket capacity (Poisson mean 11.2)
#define MASK_WORDS 256             // 8192 bits per row
#define NBLK       256             // pairs grid: 32 rows (warps) per block
#define NTHR       1024
#define ROWS       32
#define CHUNK      48              // jlist chunk (rows avg ~47 hits, max ~80)
#define FULLMASK   0xffffffffu

// Scratch (device globals; zero at module load). Invariants per replay:
//   g_cell_cnt: zeroed by pairs_kernel tail phase of the PREVIOUS run
//   g_state:    zeroed by build_kernel of the CURRENT run (before pairs)
__device__ int      g_cell_cnt[NCELLS];
__device__ float4   g_bpos[NCELLS * CAP];    // (x, y, z, atom_idx bits)
__device__ int      g_bbatch[NCELLS * CAP];
__device__ unsigned g_state[NBLK];           // decoupled-lookback state

// d2 with the SAME rounding as the reference: rounded products, then ((a+b)+c).
__device__ __forceinline__ float d2_exact(float dx, float dy, float dz) {
    float a = __fmul_rn(dx, dx);
    float b = __fmul_rn(dy, dy);
    float c = __fmul_rn(dz, dz);
    return __fadd_rn(__fadd_rn(a, b), c);
}

__device__ __forceinline__ int cell_coord(float p) {
    int c = (int)(p * 0.2f);
    return c < 0 ? 0 : (c > NCELL1 - 1 ? NCELL1 - 1 : c);
}

// ---------------------------------------------------------------------------
// K1: bucketed cell-list build + g_state reset (stream-ordered before pairs).
// ---------------------------------------------------------------------------
__global__ void build_kernel(const float* __restrict__ pos,
                             const int*   __restrict__ batch) {
    const int i = blockIdx.x * blockDim.x + threadIdx.x;
    if (i < NBLK) g_state[i] = 0u;           // reset lookback state
    if (i >= NATOMS) return;
    const float x = pos[3 * i + 0];
    const float y = pos[3 * i + 1];
    const float z = pos[3 * i + 2];
    const int c = cell_coord(x) * 81 + cell_coord(y) * 9 + cell_coord(z);
    const int slot = atomicAdd(&g_cell_cnt[c], 1);
    if (slot < CAP) {
        g_bpos[c * CAP + slot]   = make_float4(x, y, z, __int_as_float(i));
        g_bbatch[c * CAP + slot] = batch[i];
    }
}

// ---------------------------------------------------------------------------
// K2: fused count + scan (decoupled lookback) + ordered write + tail fill.
// 256 blocks x 1024 threads, launch_bounds(1024,2): all blocks co-resident
// (2/SM x 148 = 296 >= 256) so the forward poll on g_state[255] is
// deadlock-free, and its flag=2 implies every block finished its eval phase.
//
// NEW vs R12: warp-balanced write phase. Hits are extracted (rank-ordered)
// into a shared jlist in CHUNK-sized batches, then all 32 lanes consume the
// list strided -> coalesced outI/outJ/outW stores, ~1.5 write iterations per
// lane instead of max-lane ~6, and 32-wide MLP on the pos[j] re-reads.
// ---------------------------------------------------------------------------
__global__ void __launch_bounds__(NTHR, 2)
pairs_kernel(const float* __restrict__ pos,
             const int*   __restrict__ batch,
             float*       __restrict__ out) {
    __shared__ unsigned smask[ROWS][MASK_WORDS];   // 32 KB
    __shared__ int scum[ROWS][32];                 // per-warp cell cum table
    __shared__ int sbase[ROWS][32];                // per-warp (cell*CAP - cum)
    __shared__ int sjlist[ROWS][CHUNK];            // 6 KB rank-ordered j list
    __shared__ int scnt[ROWS];
    __shared__ int srowoff[ROWS];
    __shared__ int stotal;
    const int warp = threadIdx.x >> 5;
    const int lane = threadIdx.x & 31;
    const int b = blockIdx.x;
    const int i = b * ROWS + warp;

    #pragma unroll
    for (int k = lane; k < MASK_WORDS; k += 32) smask[warp][k] = 0;

    const float pix = pos[3 * i + 0];
    const float piy = pos[3 * i + 1];
    const float piz = pos[3 * i + 2];
    const int   bi  = batch[i];
    __syncwarp();

    const int cx = cell_coord(pix), cy = cell_coord(piy), cz = cell_coord(piz);
    const int x0 = max(cx - 1, 0), x1 = min(cx + 1, NCELL1 - 1);
    const int y0 = max(cy - 1, 0), y1 = min(cy + 1, NCELL1 - 1);
    const int z0 = max(cz - 1, 0), z1 = min(cz + 1, NCELL1 - 1);
    const int nyc = y1 - y0 + 1;
    const int nzc = z1 - z0 + 1;
    const int nyz = nyc * nzc;
    const int ncells = (x1 - x0 + 1) * nyz;

    // ---- flattened cell table (one lane per neighbor cell) + box culling ---
    int cnt_l = 0, base_l = 0;
    if (lane < ncells) {
        const int lx  = lane / nyz;
        const int rem = lane - lx * nyz;
        const int ly  = rem / nzc;
        const int lz  = rem - ly * nzc;
        const int X = x0 + lx, Y = y0 + ly, Z = z0 + lz;
        // point-to-box min distance (conservative: 1e-3 slack for rounding)
        const float lox = 5.0f * X, hix = lox + 5.0f;
        const float loy = 5.0f * Y, hiy = loy + 5.0f;
        const float loz = 5.0f * Z, hiz = loz + 5.0f;
        const float ddx = fmaxf(fmaxf(lox - pix, pix - hix), 0.0f);
        const float ddy = fmaxf(fmaxf(loy - piy, piy - hiy), 0.0f);
        const float ddz = fmaxf(fmaxf(loz - piz, piz - hiz), 0.0f);
        const float d2min = ddx * ddx + ddy * ddy + ddz * ddz;
        const int cell = X * 81 + Y * 9 + Z;
        if (d2min < CUT2 + 1e-3f) {
            int c = g_cell_cnt[cell];
            cnt_l = c > CAP ? CAP : c;
        }
        base_l = cell * CAP;
    }
    int incl = cnt_l;
    #pragma unroll
    for (int d = 1; d < 32; d <<= 1) {
        const int u = __shfl_up_sync(FULLMASK, incl, d);
        if (lane >= d) incl += u;
    }
    scum[warp][lane]  = incl - cnt_l;            // lanes >= ncells hold tot
    sbase[warp][lane] = base_l - (incl - cnt_l); // slot = sbase[k] + s
    const int tot = __shfl_sync(FULLMASK, incl, 31);
    __syncwarp();

    unsigned* __restrict__ mask = smask[warp];
    const int* __restrict__ cum = scum[warp];
    const int* __restrict__ sb  = sbase[warp];

    // ---- flat candidate loop: bisect cum table; count hits inline ----
    int hits = 0;
    for (int s = lane; s < tot; s += 32) {
        int k = 0;
        if (cum[k + 16] <= s) k += 16;
        if (cum[k + 8]  <= s) k += 8;
        if (cum[k + 4]  <= s) k += 4;
        if (cum[k + 2]  <= s) k += 2;
        if (cum[k + 1]  <= s) k += 1;
        const int slot = sb[k] + s;
        const float4 pj = g_bpos[slot];
        const float dx = pix - pj.x;
        const float dy = piy - pj.y;
        const float dz = piz - pj.z;
        const float d2 = d2_exact(dx, dy, dz);
        const int j = __float_as_int(pj.w);
        if (d2 < CUT2 && j != i && g_bbatch[slot] == bi) {
            atomicOr(&mask[j >> 5], 1u << (j & 31));
            hits++;
        }
    }
    // per-row count = total hits (each (i,j) evaluated exactly once)
    const int cnt = __reduce_add_sync(FULLMASK, hits);
    if (lane == 0) scnt[warp] = cnt;
    __syncthreads();

    // warp 0: publish aggregate, decoupled lookback, publish inclusive prefix
    if (warp == 0) {
        const int myc0 = scnt[lane];             // lane l owns row b*32+l
        int inc2 = myc0;
        #pragma unroll
        for (int d = 1; d < 32; d <<= 1) {
            const int u = __shfl_up_sync(FULLMASK, inc2, d);
            if (lane >= d) inc2 += u;
        }
        const int agg = __shfl_sync(FULLMASK, inc2, 31);
        if (lane == 0) atomicExch(&g_state[b], (1u << 30) | (unsigned)agg);

        int excl = 0;
        int look = b - 1;
        bool done = (look < 0);
        while (!done) {
            const int idx = look - lane;
            unsigned v;
            if (idx >= 0) {
                do { v = *(volatile unsigned*)&g_state[idx]; } while (v == 0u);
            } else {
                v = (2u << 30);               // virtual PREFIX=0 before block 0
            }
            const unsigned flag = v >> 30;
            const int val = (int)(v & 0x3FFFFFFFu);
            const unsigned pmask = __ballot_sync(FULLMASK, flag == 2u);
            const int limit = (pmask != 0u) ? (__ffs(pmask) - 1) : 31;
            int contrib = (lane <= limit) ? val : 0;
            #pragma unroll
            for (int d = 16; d > 0; d >>= 1)
                contrib += __shfl_down_sync(FULLMASK, contrib, d);
            contrib = __shfl_sync(FULLMASK, contrib, 0);
            excl += contrib;
            if (pmask != 0u) done = true; else look -= 32;
        }
        if (lane == 0)
            atomicExch(&g_state[b], (2u << 30) | (unsigned)(excl + agg));
        srowoff[lane] = excl + inc2 - myc0;      // global exclusive row offset
    }
    __syncthreads();

    // ---- warp-balanced ordered write via shared jlist, CHUNK at a time ----
    // lane l owns words [8l, 8l+8) -> j in [256l, 256(l+1)); ranks ascend
    int myc = 0;
    #pragma unroll
    for (int t = 0; t < 8; t++) myc += __popc(mask[lane * 8 + t]);

    int inclw = myc;
    #pragma unroll
    for (int d = 1; d < 32; d <<= 1) {
        const int u = __shfl_up_sync(FULLMASK, inclw, d);
        if (lane >= d) inclw += u;
    }
    const int rb = inclw - myc;                  // lane's rank base in row

    const float fi = (float)i;
    const int rowoff = srowoff[warp];
    int* __restrict__ jl = sjlist[warp];
    float* __restrict__ outI = out;
    float* __restrict__ outJ = out + MAX_PAIRS;
    float* __restrict__ outW = out + 2 * MAX_PAIRS;
    float* __restrict__ outV = out + 3 * MAX_PAIRS;

    for (int cb = 0; cb < cnt; cb += CHUNK) {
        const int ce = (cb + CHUNK < cnt) ? (cb + CHUNK) : cnt;
        // extract this lane's bits whose global rank falls in [cb, ce)
        if (rb < ce && rb + myc > cb) {
            int r = rb;
            #pragma unroll
            for (int t = 0; t < 8; t++) {
                if (r >= ce) break;
                unsigned word = mask[lane * 8 + t];
                const int pc = __popc(word);
                if (r + pc <= cb) { r += pc; continue; }
                const int jbase = (lane * 8 + t) * 32;
                while (word && r < ce) {
                    const int bpos = __ffs(word) - 1;
                    word &= word - 1;
                    if (r >= cb) jl[r - cb] = jbase + bpos;
                    r++;
                }
            }
        }
        __syncwarp();
        // balanced, coalesced consumption
        const int m = ce - cb;
        for (int h = lane; h < m; h += 32) {
            const int j = jl[h];
            const int p = rowoff + cb + h;
            const float dx = pix - pos[3 * j + 0];
            const float dy = piy - pos[3 * j + 1];
            const float dz = piz - pos[3 * j + 2];
            const float d2 = d2_exact(dx, dy, dz);
            if (p < MAX_PAIRS) {
                outI[p] = fi;
                outJ[p] = (float)j;
                outW[p] = sqrtf(d2);
                outV[3 * p + 0] = dx;
                outV[3 * p + 1] = dy;
                outV[3 * p + 2] = dz;
            }
        }
        __syncwarp();
    }

    // ---- tail phase: forward-poll the final prefix (safe: co-resident grid)
    if (threadIdx.x == 0) {
        unsigned v;
        do { v = *(volatile unsigned*)&g_state[NBLK - 1]; }
        while ((v >> 30) != 2u);
        stotal = (int)(v & 0x3FFFFFFFu);
    }
    __syncthreads();
    int total = stotal;
    if (total > MAX_PAIRS) total = MAX_PAIRS;

    // restore g_cell_cnt for the next replay (all evals finished by now)
    if (b == 0) {
        for (int k = threadIdx.x; k < NCELLS; k += NTHR) g_cell_cnt[k] = 0;
    }

    // fill invalid tail [total, MAX_PAIRS): index=-1, weight=0, vec=0
    for (int q = total + b * NTHR + threadIdx.x; q < MAX_PAIRS; q += NBLK * NTHR) {
        outI[q] = -1.0f;
        outJ[q] = -1.0f;
        outW[q] = 0.0f;
        outV[3 * q + 0] = 0.0f;
        outV[3 * q + 1] = 0.0f;
        outV[3 * q + 2] = 0.0f;
    }
}

// ---------------------------------------------------------------------------
extern "C" void kernel_launch(void* const* d_in, const int* in_sizes, int n_in,
                              void* d_out, int out_size) {
    const float* pos   = (const float*)d_in[0];   // [8192, 3] f32
    const int*   batch = (const int*)d_in[1];     // [8192] i32
    float* out = (float*)d_out;                   // 6 * MAX_PAIRS floats

    (void)in_sizes; (void)n_in; (void)out_size;

    build_kernel<<<NATOMS / 64, 64>>>(pos, batch);
    pairs_kernel<<<NBLK, NTHR>>>(pos, batch, out);
}

// round 14
// speedup vs baseline: 1.0623x; 1.0346x over previous
#include <cuda_runtime.h>
#include <math.h>

// Problem constants (fixed by the reference)
#define NATOMS     8192
#define MAX_PAIRS  (64 * 8192)     // 524288
#define CUT2       25.0f           // cutoff_upper^2; cutoff_lower = 0
#define NCELL1     9               // 45.0 / 5.0
#define NCELLS     (NCELL1 * NCELL1 * NCELL1)   // 729
#define CAP        48              // bucket capacity (Poisson mean 11.2)
#define MASK_WORDS 256             // 8192 bits per row
#define NBLK       512             // pairs grid: 16 rows (warps) per block
#define NTHR       512
#define ROWS       16
#define MAXTOT     512             // direct slot-table capacity per row
#define CHUNK      48              // jlist chunk (rows avg ~47 hits, max ~80)
#define FULLMASK   0xffffffffu

// Scratch (device globals; zero at module load). Invariants per replay:
//   g_cell_cnt: zeroed by pairs_kernel tail phase of the PREVIOUS run
//   g_state:    zeroed by build_kernel of the CURRENT run (before pairs)
__device__ int      g_cell_cnt[NCELLS];
__device__ float4   g_bpos[NCELLS * CAP];    // (x, y, z, atom_idx bits)
__device__ int      g_bbatch[NCELLS * CAP];
__device__ unsigned g_state[NBLK];           // decoupled-lookback state

// d2 with the SAME rounding as the reference: rounded products, then ((a+b)+c).
__device__ __forceinline__ float d2_exact(float dx, float dy, float dz) {
    float a = __fmul_rn(dx, dx);
    float b = __fmul_rn(dy, dy);
    float c = __fmul_rn(dz, dz);
    return __fadd_rn(__fadd_rn(a, b), c);
}

__device__ __forceinline__ int cell_coord(float p) {
    int c = (int)(p * 0.2f);
    return c < 0 ? 0 : (c > NCELL1 - 1 ? NCELL1 - 1 : c);
}

// ---------------------------------------------------------------------------
// K1: bucketed cell-list build + g_state reset (stream-ordered before pairs).
// ---------------------------------------------------------------------------
__global__ void build_kernel(const float* __restrict__ pos,
                             const int*   __restrict__ batch) {
    const int i = blockIdx.x * blockDim.x + threadIdx.x;
    if (i < NBLK) g_state[i] = 0u;           // reset lookback state
    if (i >= NATOMS) return;
    const float x = pos[3 * i + 0];
    const float y = pos[3 * i + 1];
    const float z = pos[3 * i + 2];
    const int c = cell_coord(x) * 81 + cell_coord(y) * 9 + cell_coord(z);
    const int slot = atomicAdd(&g_cell_cnt[c], 1);
    if (slot < CAP) {
        g_bpos[c * CAP + slot]   = make_float4(x, y, z, __int_as_float(i));
        g_bbatch[c * CAP + slot] = batch[i];
    }
}

// ---------------------------------------------------------------------------
// K2: fused count + scan (decoupled lookback) + ordered write + tail fill.
// 512 blocks x 512 threads, launch_bounds(512,4): 4/SM x 148 = 592 >= 512,
// all blocks co-resident -> forward poll on g_state[511] is deadlock-free,
// and flag=2 there implies every block finished its eval phase.
//
// NEW vs R13: direct slot table. Each of the 27 cell-lanes writes its slot
// ids into stab[row][*] (uint16); the eval loop reads ONE LDS per candidate
// instead of a 5-deep dependent bisect chain. Bisect kept only as overflow
// fallback for s >= MAXTOT (essentially never: mean tot ~190).
// jlist aliases stab (stab is dead after eval; write is post-syncthreads).
// ---------------------------------------------------------------------------
__global__ void __launch_bounds__(NTHR, 4)
pairs_kernel(const float* __restrict__ pos,
             const int*   __restrict__ batch,
             float*       __restrict__ out) {
    __shared__ unsigned smask[ROWS][MASK_WORDS];       // 16 KB
    __shared__ int scum[ROWS][32];                     // 2 KB cell cum table
    __shared__ int sbase[ROWS][32];                    // 2 KB (cell*CAP - cum)
    __shared__ unsigned short stab[ROWS][MAXTOT];      // 16 KB slot table
    __shared__ int scnt[ROWS];
    __shared__ int srowoff[ROWS];
    __shared__ int stotal;
    const int warp = threadIdx.x >> 5;
    const int lane = threadIdx.x & 31;
    const int b = blockIdx.x;
    const int i = b * ROWS + warp;

    #pragma unroll
    for (int k = lane; k < MASK_WORDS; k += 32) smask[warp][k] = 0;

    const float pix = pos[3 * i + 0];
    const float piy = pos[3 * i + 1];
    const float piz = pos[3 * i + 2];
    const int   bi  = batch[i];
    __syncwarp();

    const int cx = cell_coord(pix), cy = cell_coord(piy), cz = cell_coord(piz);
    const int x0 = max(cx - 1, 0), x1 = min(cx + 1, NCELL1 - 1);
    const int y0 = max(cy - 1, 0), y1 = min(cy + 1, NCELL1 - 1);
    const int z0 = max(cz - 1, 0), z1 = min(cz + 1, NCELL1 - 1);
    const int nyc = y1 - y0 + 1;
    const int nzc = z1 - z0 + 1;
    const int nyz = nyc * nzc;
    const int ncells = (x1 - x0 + 1) * nyz;

    // ---- flattened cell table (one lane per neighbor cell) + box culling ---
    int cnt_l = 0, base_l = 0;
    if (lane < ncells) {
        const int lx  = lane / nyz;
        const int rem = lane - lx * nyz;
        const int ly  = rem / nzc;
        const int lz  = rem - ly * nzc;
        const int X = x0 + lx, Y = y0 + ly, Z = z0 + lz;
        // point-to-box min distance (conservative: 1e-3 slack for rounding)
        const float lox = 5.0f * X, hix = lox + 5.0f;
        const float loy = 5.0f * Y, hiy = loy + 5.0f;
        const float loz = 5.0f * Z, hiz = loz + 5.0f;
        const float ddx = fmaxf(fmaxf(lox - pix, pix - hix), 0.0f);
        const float ddy = fmaxf(fmaxf(loy - piy, piy - hiy), 0.0f);
        const float ddz = fmaxf(fmaxf(loz - piz, piz - hiz), 0.0f);
        const float d2min = ddx * ddx + ddy * ddy + ddz * ddz;
        const int cell = X * 81 + Y * 9 + Z;
        if (d2min < CUT2 + 1e-3f) {
            int c = g_cell_cnt[cell];
            cnt_l = c > CAP ? CAP : c;
        }
        base_l = cell * CAP;
    }
    int incl = cnt_l;
    #pragma unroll
    for (int d = 1; d < 32; d <<= 1) {
        const int u = __shfl_up_sync(FULLMASK, incl, d);
        if (lane >= d) incl += u;
    }
    const int cum_l = incl - cnt_l;
    scum[warp][lane]  = cum_l;                   // lanes >= ncells hold tot
    sbase[warp][lane] = base_l - cum_l;          // fallback: slot = sbase[k]+s
    const int tot = __shfl_sync(FULLMASK, incl, 31);

    // ---- direct slot table: lane writes its cell's slot ids ----
    unsigned short* __restrict__ st = stab[warp];
    for (int o = 0; o < cnt_l; o++) {
        const int idx = cum_l + o;
        if (idx < MAXTOT) st[idx] = (unsigned short)(base_l + o);
    }
    __syncwarp();

    unsigned* __restrict__ mask = smask[warp];
    const int* __restrict__ cum = scum[warp];
    const int* __restrict__ sb  = sbase[warp];

    // ---- flat candidate loop: ONE LDS per candidate; count hits inline ----
    int hits = 0;
    for (int s = lane; s < tot; s += 32) {
        int slot;
        if (s < MAXTOT) {
            slot = st[s];
        } else {                                  // overflow fallback (rare)
            int k = 0;
            if (cum[k + 16] <= s) k += 16;
            if (cum[k + 8]  <= s) k += 8;
            if (cum[k + 4]  <= s) k += 4;
            if (cum[k + 2]  <= s) k += 2;
            if (cum[k + 1]  <= s) k += 1;
            slot = sb[k] + s;
        }
        const float4 pj = g_bpos[slot];
        const float dx = pix - pj.x;
        const float dy = piy - pj.y;
        const float dz = piz - pj.z;
        const float d2 = d2_exact(dx, dy, dz);
        const int j = __float_as_int(pj.w);
        if (d2 < CUT2 && j != i && g_bbatch[slot] == bi) {
            atomicOr(&mask[j >> 5], 1u << (j & 31));
            hits++;
        }
    }
    // per-row count = total hits (each (i,j) evaluated exactly once)
    const int cnt = __reduce_add_sync(FULLMASK, hits);
    if (lane == 0) scnt[warp] = cnt;
    __syncthreads();

    // warp 0: publish aggregate, decoupled lookback, publish inclusive prefix
    if (warp == 0) {
        const int myc0 = (lane < ROWS) ? scnt[lane] : 0;
        int inc2 = myc0;
        #pragma unroll
        for (int d = 1; d < 32; d <<= 1) {
            const int u = __shfl_up_sync(FULLMASK, inc2, d);
            if (lane >= d) inc2 += u;
        }
        const int agg = __shfl_sync(FULLMASK, inc2, 31);
        if (lane == 0) atomicExch(&g_state[b], (1u << 30) | (unsigned)agg);

        int excl = 0;
        int look = b - 1;
        bool done = (look < 0);
        while (!done) {
            const int idx = look - lane;
            unsigned v;
            if (idx >= 0) {
                do { v = *(volatile unsigned*)&g_state[idx]; } while (v == 0u);
            } else {
                v = (2u << 30);               // virtual PREFIX=0 before block 0
            }
            const unsigned flag = v >> 30;
            const int val = (int)(v & 0x3FFFFFFFu);
            const unsigned pmask = __ballot_sync(FULLMASK, flag == 2u);
            const int limit = (pmask != 0u) ? (__ffs(pmask) - 1) : 31;
            int contrib = (lane <= limit) ? val : 0;
            #pragma unroll
            for (int d = 16; d > 0; d >>= 1)
                contrib += __shfl_down_sync(FULLMASK, contrib, d);
            contrib = __shfl_sync(FULLMASK, contrib, 0);
            excl += contrib;
            if (pmask != 0u) done = true; else look -= 32;
        }
        if (lane == 0)
            atomicExch(&g_state[b], (2u << 30) | (unsigned)(excl + agg));
        if (lane < ROWS) srowoff[lane] = excl + inc2 - myc0;
    }
    __syncthreads();

    // ---- warp-balanced ordered write via jlist (aliases dead stab row) ----
    // lane l owns words [8l, 8l+8) -> j in [256l, 256(l+1)); ranks ascend
    int myc = 0;
    #pragma unroll
    for (int t = 0; t < 8; t++) myc += __popc(mask[lane * 8 + t]);

    int inclw = myc;
    #pragma unroll
    for (int d = 1; d < 32; d <<= 1) {
        const int u = __shfl_up_sync(FULLMASK, inclw, d);
        if (lane >= d) inclw += u;
    }
    const int rb = inclw - myc;                  // lane's rank base in row

    const float fi = (float)i;
    const int rowoff = srowoff[warp];
    int* __restrict__ jl = reinterpret_cast<int*>(stab[warp]);  // 192B < 1KB
    float* __restrict__ outI = out;
    float* __restrict__ outJ = out + MAX_PAIRS;
    float* __restrict__ outW = out + 2 * MAX_PAIRS;
    float* __restrict__ outV = out + 3 * MAX_PAIRS;

    for (int cb = 0; cb < cnt; cb += CHUNK) {
        const int ce = (cb + CHUNK < cnt) ? (cb + CHUNK) : cnt;
        // extract this lane's bits whose global rank falls in [cb, ce)
        if (rb < ce && rb + myc > cb) {
            int r = rb;
            #pragma unroll
            for (int t = 0; t < 8; t++) {
                if (r >= ce) break;
                unsigned word = mask[lane * 8 + t];
                const int pc = __popc(word);
                if (r + pc <= cb) { r += pc; continue; }
                const int jbase = (lane * 8 + t) * 32;
                while (word && r < ce) {
                    const int bpos = __ffs(word) - 1;
                    word &= word - 1;
                    if (r >= cb) jl[r - cb] = jbase + bpos;
                    r++;
                }
            }
        }
        __syncwarp();
        // balanced, coalesced consumption
        const int m = ce - cb;
        for (int h = lane; h < m; h += 32) {
            const int j = jl[h];
            const int p = rowoff + cb + h;
            const float dx = pix - pos[3 * j + 0];
            const float dy = piy - pos[3 * j + 1];
            const float dz = piz - pos[3 * j + 2];
            const float d2 = d2_exact(dx, dy, dz);
            if (p < MAX_PAIRS) {
                outI[p] = fi;
                outJ[p] = (float)j;
                outW[p] = sqrtf(d2);
                outV[3 * p + 0] = dx;
                outV[3 * p + 1] = dy;
                outV[3 * p + 2] = dz;
            }
        }
        __syncwarp();
    }

    // ---- tail phase: forward-poll the final prefix (safe: co-resident grid)
    if (threadIdx.x == 0) {
        unsigned v;
        do { v = *(volatile unsigned*)&g_state[NBLK - 1]; }
        while ((v >> 30) != 2u);
        stotal = (int)(v & 0x3FFFFFFFu);
    }
    __syncthreads();
    int total = stotal;
    if (total > MAX_PAIRS) total = MAX_PAIRS;

    // restore g_cell_cnt for the next replay (all evals finished by now)
    if (b == 0) {
        for (int k = threadIdx.x; k < NCELLS; k += NTHR) g_cell_cnt[k] = 0;
    }

    // fill invalid tail [total, MAX_PAIRS): index=-1, weight=0, vec=0
    for (int q = total + b * NTHR + threadIdx.x; q < MAX_PAIRS; q += NBLK * NTHR) {
        outI[q] = -1.0f;
        outJ[q] = -1.0f;
        outW[q] = 0.0f;
        outV[3 * q + 0] = 0.0f;
        outV[3 * q + 1] = 0.0f;
        outV[3 * q + 2] = 0.0f;
    }
}

// ---------------------------------------------------------------------------
extern "C" void kernel_launch(void* const* d_in, const int* in_sizes, int n_in,
                              void* d_out, int out_size) {
    const float* pos   = (const float*)d_in[0];   // [8192, 3] f32
    const int*   batch = (const int*)d_in[1];     // [8192] i32
    float* out = (float*)d_out;                   // 6 * MAX_PAIRS floats

    (void)in_sizes; (void)n_in; (void)out_size;

    build_kernel<<<NATOMS / 64, 64>>>(pos, batch);
    pairs_kernel<<<NBLK, NTHR>>>(pos, batch, out);
}

// round 15
// speedup vs baseline: 1.1585x; 1.0906x over previous
#include <cuda_runtime.h>
#include <math.h>

// Problem constants (fixed by the reference)
#define NATOMS     8192
#define MAX_PAIRS  (64 * 8192)     // 524288
#define CUT2       25.0f           // cutoff_upper^2; cutoff_lower = 0
#define NCELL1     9               // 45.0 / 5.0
#define NCELLS     (NCELL1 * NCELL1 * NCELL1)   // 729
#define CAP        48              // bucket capacity (Poisson mean 11.2)
#define MASK_WORDS 256             // 8192 bits per row
#define NBLK       512             // pairs grid: 16 rows (warps) per block
#define NTHR       512
#define ROWS       16
#define MAXTOT     512             // direct slot-table capacity per row
#define CHUNK      48              // jlist chunk (rows avg ~47 hits, max ~80)
#define FULLMASK   0xffffffffu

// Scratch (device globals; zero at module load). Invariants per replay:
//   g_cell_cnt: zeroed by pairs_kernel tail phase of the PREVIOUS run
//   g_state:    zeroed by build_kernel of the CURRENT run (before pairs)
__device__ int      g_cell_cnt[NCELLS];
__device__ float4   g_bpos[NCELLS * CAP];    // (x, y, z, atom_idx bits)
__device__ int      g_bbatch[NCELLS * CAP];
__device__ unsigned g_state[NBLK];           // decoupled-lookback state

// d2 with the SAME rounding as the reference: rounded products, then ((a+b)+c).
__device__ __forceinline__ float d2_exact(float dx, float dy, float dz) {
    float a = __fmul_rn(dx, dx);
    float b = __fmul_rn(dy, dy);
    float c = __fmul_rn(dz, dz);
    return __fadd_rn(__fadd_rn(a, b), c);
}

__device__ __forceinline__ int cell_coord(float p) {
    int c = (int)(p * 0.2f);
    return c < 0 ? 0 : (c > NCELL1 - 1 ? NCELL1 - 1 : c);
}

// ---------------------------------------------------------------------------
// K1: bucketed cell-list build + g_state reset (stream-ordered before pairs).
// ---------------------------------------------------------------------------
__global__ void build_kernel(const float* __restrict__ pos,
                             const int*   __restrict__ batch) {
    const int i = blockIdx.x * blockDim.x + threadIdx.x;
    if (i < NBLK) g_state[i] = 0u;           // reset lookback state
    if (i >= NATOMS) return;
    const float x = pos[3 * i + 0];
    const float y = pos[3 * i + 1];
    const float z = pos[3 * i + 2];
    const int c = cell_coord(x) * 81 + cell_coord(y) * 9 + cell_coord(z);
    const int slot = atomicAdd(&g_cell_cnt[c], 1);
    if (slot < CAP) {
        g_bpos[c * CAP + slot]   = make_float4(x, y, z, __int_as_float(i));
        g_bbatch[c * CAP + slot] = batch[i];
    }
}

// ---------------------------------------------------------------------------
// K2: fused count + scan (decoupled lookback) + ordered write + tail fill.
// 512 blocks x 512 threads, launch_bounds(512,4): 4/SM x 148 = 592 >= 512,
// all blocks co-resident -> forward poll on g_state[511] is deadlock-free.
//
// NEW vs R14: eval-loop latency chain cut ~2x:
//  - g_bbatch loaded unconditionally, issued WITH g_bpos (no dependent load)
//  - 2-way ILP: candidates s and s+32 per trip, all loads issued before use
// ---------------------------------------------------------------------------
__global__ void __launch_bounds__(NTHR, 4)
pairs_kernel(const float* __restrict__ pos,
             const int*   __restrict__ batch,
             float*       __restrict__ out) {
    __shared__ unsigned smask[ROWS][MASK_WORDS];       // 16 KB
    __shared__ int scum[ROWS][32];                     // 2 KB cell cum table
    __shared__ int sbase[ROWS][32];                    // 2 KB (cell*CAP - cum)
    __shared__ unsigned short stab[ROWS][MAXTOT];      // 16 KB slot table
    __shared__ int scnt[ROWS];
    __shared__ int srowoff[ROWS];
    __shared__ int stotal;
    const int warp = threadIdx.x >> 5;
    const int lane = threadIdx.x & 31;
    const int b = blockIdx.x;
    const int i = b * ROWS + warp;

    #pragma unroll
    for (int k = lane; k < MASK_WORDS; k += 32) smask[warp][k] = 0;

    const float pix = pos[3 * i + 0];
    const float piy = pos[3 * i + 1];
    const float piz = pos[3 * i + 2];
    const int   bi  = batch[i];
    __syncwarp();

    const int cx = cell_coord(pix), cy = cell_coord(piy), cz = cell_coord(piz);
    const int x0 = max(cx - 1, 0), x1 = min(cx + 1, NCELL1 - 1);
    const int y0 = max(cy - 1, 0), y1 = min(cy + 1, NCELL1 - 1);
    const int z0 = max(cz - 1, 0), z1 = min(cz + 1, NCELL1 - 1);
    const int nyc = y1 - y0 + 1;
    const int nzc = z1 - z0 + 1;
    const int nyz = nyc * nzc;
    const int ncells = (x1 - x0 + 1) * nyz;

    // ---- flattened cell table (one lane per neighbor cell) + box culling ---
    int cnt_l = 0, base_l = 0;
    if (lane < ncells) {
        const int lx  = lane / nyz;
        const int rem = lane - lx * nyz;
        const int ly  = rem / nzc;
        const int lz  = rem - ly * nzc;
        const int X = x0 + lx, Y = y0 + ly, Z = z0 + lz;
        // point-to-box min distance (conservative: 1e-3 slack for rounding)
        const float lox = 5.0f * X, hix = lox + 5.0f;
        const float loy = 5.0f * Y, hiy = loy + 5.0f;
        const float loz = 5.0f * Z, hiz = loz + 5.0f;
        const float ddx = fmaxf(fmaxf(lox - pix, pix - hix), 0.0f);
        const float ddy = fmaxf(fmaxf(loy - piy, piy - hiy), 0.0f);
        const float ddz = fmaxf(fmaxf(loz - piz, piz - hiz), 0.0f);
        const float d2min = ddx * ddx + ddy * ddy + ddz * ddz;
        const int cell = X * 81 + Y * 9 + Z;
        if (d2min < CUT2 + 1e-3f) {
            int c = g_cell_cnt[cell];
            cnt_l = c > CAP ? CAP : c;
        }
        base_l = cell * CAP;
    }
    int incl = cnt_l;
    #pragma unroll
    for (int d = 1; d < 32; d <<= 1) {
        const int u = __shfl_up_sync(FULLMASK, incl, d);
        if (lane >= d) incl += u;
    }
    const int cum_l = incl - cnt_l;
    scum[warp][lane]  = cum_l;                   // lanes >= ncells hold tot
    sbase[warp][lane] = base_l - cum_l;          // fallback: slot = sbase[k]+s
    const int tot = __shfl_sync(FULLMASK, incl, 31);

    // ---- direct slot table: lane writes its cell's slot ids ----
    unsigned short* __restrict__ st = stab[warp];
    if (tot <= MAXTOT) {
        for (int o = 0; o < cnt_l; o++) st[cum_l + o] = (unsigned short)(base_l + o);
    }
    __syncwarp();

    unsigned* __restrict__ mask = smask[warp];

    // ---- flat candidate loop: 2-way ILP, all loads issued up front ----
    int hits = 0;
    if (tot <= MAXTOT) {
        int s = lane;
        for (; s + 32 < tot; s += 64) {
            const int slotA = st[s];
            const int slotB = st[s + 32];
            const float4 pA = g_bpos[slotA];
            const float4 pB = g_bpos[slotB];
            const int bA = g_bbatch[slotA];
            const int bB = g_bbatch[slotB];
            {
                const float dx = pix - pA.x;
                const float dy = piy - pA.y;
                const float dz = piz - pA.z;
                const float d2 = d2_exact(dx, dy, dz);
                const int j = __float_as_int(pA.w);
                if (d2 < CUT2 && j != i && bA == bi) {
                    atomicOr(&mask[j >> 5], 1u << (j & 31));
                    hits++;
                }
            }
            {
                const float dx = pix - pB.x;
                const float dy = piy - pB.y;
                const float dz = piz - pB.z;
                const float d2 = d2_exact(dx, dy, dz);
                const int j = __float_as_int(pB.w);
                if (d2 < CUT2 && j != i && bB == bi) {
                    atomicOr(&mask[j >> 5], 1u << (j & 31));
                    hits++;
                }
            }
        }
        if (s < tot) {
            const int slot = st[s];
            const float4 pj = g_bpos[slot];
            const int bj = g_bbatch[slot];
            const float dx = pix - pj.x;
            const float dy = piy - pj.y;
            const float dz = piz - pj.z;
            const float d2 = d2_exact(dx, dy, dz);
            const int j = __float_as_int(pj.w);
            if (d2 < CUT2 && j != i && bj == bi) {
                atomicOr(&mask[j >> 5], 1u << (j & 31));
                hits++;
            }
        }
    } else {
        // overflow fallback (essentially never): bisect the cum table
        const int* __restrict__ cum = scum[warp];
        const int* __restrict__ sb  = sbase[warp];
        for (int s = lane; s < tot; s += 32) {
            int k = 0;
            if (cum[k + 16] <= s) k += 16;
            if (cum[k + 8]  <= s) k += 8;
            if (cum[k + 4]  <= s) k += 4;
            if (cum[k + 2]  <= s) k += 2;
            if (cum[k + 1]  <= s) k += 1;
            const int slot = sb[k] + s;
            const float4 pj = g_bpos[slot];
            const int bj = g_bbatch[slot];
            const float dx = pix - pj.x;
            const float dy = piy - pj.y;
            const float dz = piz - pj.z;
            const float d2 = d2_exact(dx, dy, dz);
            const int j = __float_as_int(pj.w);
            if (d2 < CUT2 && j != i && bj == bi) {
                atomicOr(&mask[j >> 5], 1u << (j & 31));
                hits++;
            }
        }
    }
    // per-row count = total hits (each (i,j) evaluated exactly once)
    const int cnt = __reduce_add_sync(FULLMASK, hits);
    if (lane == 0) scnt[warp] = cnt;
    __syncthreads();

    // warp 0: publish aggregate, decoupled lookback, publish inclusive prefix
    if (warp == 0) {
        const int myc0 = (lane < ROWS) ? scnt[lane] : 0;
        int inc2 = myc0;
        #pragma unroll
        for (int d = 1; d < 32; d <<= 1) {
            const int u = __shfl_up_sync(FULLMASK, inc2, d);
            if (lane >= d) inc2 += u;
        }
        const int agg = __shfl_sync(FULLMASK, inc2, 31);
        if (lane == 0) atomicExch(&g_state[b], (1u << 30) | (unsigned)agg);

        int excl = 0;
        int look = b - 1;
        bool done = (look < 0);
        while (!done) {
            const int idx = look - lane;
            unsigned v;
            if (idx >= 0) {
                do { v = *(volatile unsigned*)&g_state[idx]; } while (v == 0u);
            } else {
                v = (2u << 30);               // virtual PREFIX=0 before block 0
            }
            const unsigned flag = v >> 30;
            const int val = (int)(v & 0x3FFFFFFFu);
            const unsigned pmask = __ballot_sync(FULLMASK, flag == 2u);
            const int limit = (pmask != 0u) ? (__ffs(pmask) - 1) : 31;
            int contrib = (lane <= limit) ? val : 0;
            #pragma unroll
            for (int d = 16; d > 0; d >>= 1)
                contrib += __shfl_down_sync(FULLMASK, contrib, d);
            contrib = __shfl_sync(FULLMASK, contrib, 0);
            excl += contrib;
            if (pmask != 0u) done = true; else look -= 32;
        }
        if (lane == 0)
            atomicExch(&g_state[b], (2u << 30) | (unsigned)(excl + agg));
        if (lane < ROWS) srowoff[lane] = excl + inc2 - myc0;
    }
    __syncthreads();

    // ---- warp-balanced ordered write via jlist (aliases dead stab row) ----
    // lane l owns words [8l, 8l+8) -> j in [256l, 256(l+1)); ranks ascend
    int myc = 0;
    #pragma unroll
    for (int t = 0; t < 8; t++) myc += __popc(mask[lane * 8 + t]);

    int inclw = myc;
    #pragma unroll
    for (int d = 1; d < 32; d <<= 1) {
        const int u = __shfl_up_sync(FULLMASK, inclw, d);
        if (lane >= d) inclw += u;
    }
    const int rb = inclw - myc;                  // lane's rank base in row

    const float fi = (float)i;
    const int rowoff = srowoff[warp];
    int* __restrict__ jl = reinterpret_cast<int*>(stab[warp]);  // 192B < 1KB
    float* __restrict__ outI = out;
    float* __restrict__ outJ = out + MAX_PAIRS;
    float* __restrict__ outW = out + 2 * MAX_PAIRS;
    float* __restrict__ outV = out + 3 * MAX_PAIRS;

    for (int cb = 0; cb < cnt; cb += CHUNK) {
        const int ce = (cb + CHUNK < cnt) ? (cb + CHUNK) : cnt;
        // extract this lane's bits whose global rank falls in [cb, ce)
        if (rb < ce && rb + myc > cb) {
            int r = rb;
            #pragma unroll
            for (int t = 0; t < 8; t++) {
                if (r >= ce) break;
                unsigned word = mask[lane * 8 + t];
                const int pc = __popc(word);
                if (r + pc <= cb) { r += pc; continue; }
                const int jbase = (lane * 8 + t) * 32;
                while (word && r < ce) {
                    const int bpos = __ffs(word) - 1;
                    word &= word - 1;
                    if (r >= cb) jl[r - cb] = jbase + bpos;
                    r++;
                }
            }
        }
        __syncwarp();
        // balanced, coalesced consumption
        const int m = ce - cb;
        for (int h = lane; h < m; h += 32) {
            const int j = jl[h];
            const int p = rowoff + cb + h;
            const float dx = pix - pos[3 * j + 0];
            const float dy = piy - pos[3 * j + 1];
            const float dz = piz - pos[3 * j + 2];
            const float d2 = d2_exact(dx, dy, dz);
            if (p < MAX_PAIRS) {
                outI[p] = fi;
                outJ[p] = (float)j;
                outW[p] = sqrtf(d2);
                outV[3 * p + 0] = dx;
                outV[3 * p + 1] = dy;
                outV[3 * p + 2] = dz;
            }
        }
        __syncwarp();
    }

    // ---- tail phase: forward-poll the final prefix (safe: co-resident grid)
    if (threadIdx.x == 0) {
        unsigned v;
        do { v = *(volatile unsigned*)&g_state[NBLK - 1]; }
        while ((v >> 30) != 2u);
        stotal = (int)(v & 0x3FFFFFFFu);
    }
    __syncthreads();
    int total = stotal;
    if (total > MAX_PAIRS) total = MAX_PAIRS;

    // restore g_cell_cnt for the next replay (all evals finished by now)
    if (b == 0) {
        for (int k = threadIdx.x; k < NCELLS; k += NTHR) g_cell_cnt[k] = 0;
    }

    // fill invalid tail [total, MAX_PAIRS): index=-1, weight=0, vec=0
    for (int q = total + b * NTHR + threadIdx.x; q < MAX_PAIRS; q += NBLK * NTHR) {
        outI[q] = -1.0f;
        outJ[q] = -1.0f;
        outW[q] = 0.0f;
        outV[3 * q + 0] = 0.0f;
        outV[3 * q + 1] = 0.0f;
        outV[3 * q + 2] = 0.0f;
    }
}

// ---------------------------------------------------------------------------
extern "C" void kernel_launch(void* const* d_in, const int* in_sizes, int n_in,
                              void* d_out, int out_size) {
    const float* pos   = (const float*)d_in[0];   // [8192, 3] f32
    const int*   batch = (const int*)d_in[1];     // [8192] i32
    float* out = (float*)d_out;                   // 6 * MAX_PAIRS floats

    (void)in_sizes; (void)n_in; (void)out_size;

    build_kernel<<<NATOMS / 64, 64>>>(pos, batch);
    pairs_kernel<<<NBLK, NTHR>>>(pos, batch, out);
}

// round 16
// speedup vs baseline: 1.2809x; 1.1057x over previous
#include <cuda_runtime.h>
#include <math.h>

// Problem constants (fixed by the reference)
#define NATOMS     8192
#define MAX_PAIRS  (64 * 8192)     // 524288
#define CUT2       25.0f           // cutoff_upper^2; cutoff_lower = 0
#define NCELL1     9               // 45.0 / 5.0
#define NCELLS     (NCELL1 * NCELL1 * NCELL1)   // 729
#define CAP        48              // bucket capacity (Poisson mean 11.2)
#define MASK_WORDS 256             // 8192 bits per row
#define NBLK       512             // pairs grid: 16 rows (warps) per block
#define NTHR       512
#define ROWS       16
#define MAXTOT     512             // direct slot-table capacity per row
#define CHUNK      80              // jlist chunk (rows avg ~48 hits, max ~80)
#define FULLMASK   0xffffffffu

// Scratch (device globals; zero at module load). Invariants per replay:
//   g_cell_cnt: zeroed by pairs_kernel tail phase of the PREVIOUS run
//   g_state:    zeroed by build_kernel of the CURRENT run (before pairs)
__device__ int      g_cell_cnt[NCELLS];
__device__ float4   g_bpos[NCELLS * CAP];    // (x, y, z, atom_idx bits)
__device__ int      g_bbatch[NCELLS * CAP];
__device__ float4   g_posq[NATOMS];          // atom-indexed positions (f4)
__device__ unsigned g_state[NBLK];           // decoupled-lookback state

// d2 with the SAME rounding as the reference: rounded products, then ((a+b)+c).
__device__ __forceinline__ float d2_exact(float dx, float dy, float dz) {
    float a = __fmul_rn(dx, dx);
    float b = __fmul_rn(dy, dy);
    float c = __fmul_rn(dz, dz);
    return __fadd_rn(__fadd_rn(a, b), c);
}

__device__ __forceinline__ int cell_coord(float p) {
    int c = (int)(p * 0.2f);
    return c < 0 ? 0 : (c > NCELL1 - 1 ? NCELL1 - 1 : c);
}

// ---------------------------------------------------------------------------
// K1: bucketed cell-list build + float4 position table + g_state reset.
// ---------------------------------------------------------------------------
__global__ void build_kernel(const float* __restrict__ pos,
                             const int*   __restrict__ batch) {
    const int i = blockIdx.x * blockDim.x + threadIdx.x;
    if (i < NBLK) g_state[i] = 0u;           // reset lookback state
    if (i >= NATOMS) return;
    const float x = pos[3 * i + 0];
    const float y = pos[3 * i + 1];
    const float z = pos[3 * i + 2];
    g_posq[i] = make_float4(x, y, z, 0.0f);  // gather table for write phase
    const int c = cell_coord(x) * 81 + cell_coord(y) * 9 + cell_coord(z);
    const int slot = atomicAdd(&g_cell_cnt[c], 1);
    if (slot < CAP) {
        g_bpos[c * CAP + slot]   = make_float4(x, y, z, __int_as_float(i));
        g_bbatch[c * CAP + slot] = batch[i];
    }
}

// ---------------------------------------------------------------------------
// K2: fused count + scan (decoupled lookback) + ordered write + tail fill.
// 512 blocks x 512 threads, launch_bounds(512,4): 4/SM x 148 = 592 >= 512,
// all blocks co-resident -> forward poll on g_state[511] is deadlock-free.
//
// NEW vs R15: write-phase pos gather is ONE LDG.128 from g_posq (vs 3
// scattered scalar LDGs), and CHUNK=80 makes extraction single-pass for
// essentially every row.
// ---------------------------------------------------------------------------
__global__ void __launch_bounds__(NTHR, 4)
pairs_kernel(const float* __restrict__ pos,
             const int*   __restrict__ batch,
             float*       __restrict__ out) {
    __shared__ unsigned smask[ROWS][MASK_WORDS];       // 16 KB
    __shared__ int scum[ROWS][32];                     // 2 KB cell cum table
    __shared__ int sbase[ROWS][32];                    // 2 KB (cell*CAP - cum)
    __shared__ unsigned short stab[ROWS][MAXTOT];      // 16 KB slot table
    __shared__ int scnt[ROWS];
    __shared__ int srowoff[ROWS];
    __shared__ int stotal;
    const int warp = threadIdx.x >> 5;
    const int lane = threadIdx.x & 31;
    const int b = blockIdx.x;
    const int i = b * ROWS + warp;

    #pragma unroll
    for (int k = lane; k < MASK_WORDS; k += 32) smask[warp][k] = 0;

    const float pix = pos[3 * i + 0];
    const float piy = pos[3 * i + 1];
    const float piz = pos[3 * i + 2];
    const int   bi  = batch[i];
    __syncwarp();

    const int cx = cell_coord(pix), cy = cell_coord(piy), cz = cell_coord(piz);
    const int x0 = max(cx - 1, 0), x1 = min(cx + 1, NCELL1 - 1);
    const int y0 = max(cy - 1, 0), y1 = min(cy + 1, NCELL1 - 1);
    const int z0 = max(cz - 1, 0), z1 = min(cz + 1, NCELL1 - 1);
    const int nyc = y1 - y0 + 1;
    const int nzc = z1 - z0 + 1;
    const int nyz = nyc * nzc;
    const int ncells = (x1 - x0 + 1) * nyz;

    // ---- flattened cell table (one lane per neighbor cell) + box culling ---
    int cnt_l = 0, base_l = 0;
    if (lane < ncells) {
        const int lx  = lane / nyz;
        const int rem = lane - lx * nyz;
        const int ly  = rem / nzc;
        const int lz  = rem - ly * nzc;
        const int X = x0 + lx, Y = y0 + ly, Z = z0 + lz;
        // point-to-box min distance (conservative: 1e-3 slack for rounding)
        const float lox = 5.0f * X, hix = lox + 5.0f;
        const float loy = 5.0f * Y, hiy = loy + 5.0f;
        const float loz = 5.0f * Z, hiz = loz + 5.0f;
        const float ddx = fmaxf(fmaxf(lox - pix, pix - hix), 0.0f);
        const float ddy = fmaxf(fmaxf(loy - piy, piy - hiy), 0.0f);
        const float ddz = fmaxf(fmaxf(loz - piz, piz - hiz), 0.0f);
        const float d2min = ddx * ddx + ddy * ddy + ddz * ddz;
        const int cell = X * 81 + Y * 9 + Z;
        if (d2min < CUT2 + 1e-3f) {
            int c = g_cell_cnt[cell];
            cnt_l = c > CAP ? CAP : c;
        }
        base_l = cell * CAP;
    }
    int incl = cnt_l;
    #pragma unroll
    for (int d = 1; d < 32; d <<= 1) {
        const int u = __shfl_up_sync(FULLMASK, incl, d);
        if (lane >= d) incl += u;
    }
    const int cum_l = incl - cnt_l;
    scum[warp][lane]  = cum_l;                   // lanes >= ncells hold tot
    sbase[warp][lane] = base_l - cum_l;          // fallback: slot = sbase[k]+s
    const int tot = __shfl_sync(FULLMASK, incl, 31);

    // ---- direct slot table: lane writes its cell's slot ids ----
    unsigned short* __restrict__ st = stab[warp];
    if (tot <= MAXTOT) {
        for (int o = 0; o < cnt_l; o++) st[cum_l + o] = (unsigned short)(base_l + o);
    }
    __syncwarp();

    unsigned* __restrict__ mask = smask[warp];

    // ---- flat candidate loop: 2-way ILP, all loads issued up front ----
    int hits = 0;
    if (tot <= MAXTOT) {
        int s = lane;
        for (; s + 32 < tot; s += 64) {
            const int slotA = st[s];
            const int slotB = st[s + 32];
            const float4 pA = g_bpos[slotA];
            const float4 pB = g_bpos[slotB];
            const int bA = g_bbatch[slotA];
            const int bB = g_bbatch[slotB];
            {
                const float dx = pix - pA.x;
                const float dy = piy - pA.y;
                const float dz = piz - pA.z;
                const float d2 = d2_exact(dx, dy, dz);
                const int j = __float_as_int(pA.w);
                if (d2 < CUT2 && j != i && bA == bi) {
                    atomicOr(&mask[j >> 5], 1u << (j & 31));
                    hits++;
                }
            }
            {
                const float dx = pix - pB.x;
                const float dy = piy - pB.y;
                const float dz = piz - pB.z;
                const float d2 = d2_exact(dx, dy, dz);
                const int j = __float_as_int(pB.w);
                if (d2 < CUT2 && j != i && bB == bi) {
                    atomicOr(&mask[j >> 5], 1u << (j & 31));
                    hits++;
                }
            }
        }
        if (s < tot) {
            const int slot = st[s];
            const float4 pj = g_bpos[slot];
            const int bj = g_bbatch[slot];
            const float dx = pix - pj.x;
            const float dy = piy - pj.y;
            const float dz = piz - pj.z;
            const float d2 = d2_exact(dx, dy, dz);
            const int j = __float_as_int(pj.w);
            if (d2 < CUT2 && j != i && bj == bi) {
                atomicOr(&mask[j >> 5], 1u << (j & 31));
                hits++;
            }
        }
    } else {
        // overflow fallback (essentially never): bisect the cum table
        const int* __restrict__ cum = scum[warp];
        const int* __restrict__ sb  = sbase[warp];
        for (int s = lane; s < tot; s += 32) {
            int k = 0;
            if (cum[k + 16] <= s) k += 16;
            if (cum[k + 8]  <= s) k += 8;
            if (cum[k + 4]  <= s) k += 4;
            if (cum[k + 2]  <= s) k += 2;
            if (cum[k + 1]  <= s) k += 1;
            const int slot = sb[k] + s;
            const float4 pj = g_bpos[slot];
            const int bj = g_bbatch[slot];
            const float dx = pix - pj.x;
            const float dy = piy - pj.y;
            const float dz = piz - pj.z;
            const float d2 = d2_exact(dx, dy, dz);
            const int j = __float_as_int(pj.w);
            if (d2 < CUT2 && j != i && bj == bi) {
                atomicOr(&mask[j >> 5], 1u << (j & 31));
                hits++;
            }
        }
    }
    // per-row count = total hits (each (i,j) evaluated exactly once)
    const int cnt = __reduce_add_sync(FULLMASK, hits);
    if (lane == 0) scnt[warp] = cnt;
    __syncthreads();

    // warp 0: publish aggregate, decoupled lookback, publish inclusive prefix
    if (warp == 0) {
        const int myc0 = (lane < ROWS) ? scnt[lane] : 0;
        int inc2 = myc0;
        #pragma unroll
        for (int d = 1; d < 32; d <<= 1) {
            const int u = __shfl_up_sync(FULLMASK, inc2, d);
            if (lane >= d) inc2 += u;
        }
        const int agg = __shfl_sync(FULLMASK, inc2, 31);
        if (lane == 0) atomicExch(&g_state[b], (1u << 30) | (unsigned)agg);

        int excl = 0;
        int look = b - 1;
        bool done = (look < 0);
        while (!done) {
            const int idx = look - lane;
            unsigned v;
            if (idx >= 0) {
                do { v = *(volatile unsigned*)&g_state[idx]; } while (v == 0u);
            } else {
                v = (2u << 30);               // virtual PREFIX=0 before block 0
            }
            const unsigned flag = v >> 30;
            const int val = (int)(v & 0x3FFFFFFFu);
            const unsigned pmask = __ballot_sync(FULLMASK, flag == 2u);
            const int limit = (pmask != 0u) ? (__ffs(pmask) - 1) : 31;
            int contrib = (lane <= limit) ? val : 0;
            #pragma unroll
            for (int d = 16; d > 0; d >>= 1)
                contrib += __shfl_down_sync(FULLMASK, contrib, d);
            contrib = __shfl_sync(FULLMASK, contrib, 0);
            excl += contrib;
            if (pmask != 0u) done = true; else look -= 32;
        }
        if (lane == 0)
            atomicExch(&g_state[b], (2u << 30) | (unsigned)(excl + agg));
        if (lane < ROWS) srowoff[lane] = excl + inc2 - myc0;
    }
    __syncthreads();

    // ---- warp-balanced ordered write via jlist (aliases dead stab row) ----
    // lane l owns words [8l, 8l+8) -> j in [256l, 256(l+1)); ranks ascend
    int myc = 0;
    #pragma unroll
    for (int t = 0; t < 8; t++) myc += __popc(mask[lane * 8 + t]);

    int inclw = myc;
    #pragma unroll
    for (int d = 1; d < 32; d <<= 1) {
        const int u = __shfl_up_sync(FULLMASK, inclw, d);
        if (lane >= d) inclw += u;
    }
    const int rb = inclw - myc;                  // lane's rank base in row

    const float fi = (float)i;
    const int rowoff = srowoff[warp];
    int* __restrict__ jl = reinterpret_cast<int*>(stab[warp]);  // 320B < 1KB
    float* __restrict__ outI = out;
    float* __restrict__ outJ = out + MAX_PAIRS;
    float* __restrict__ outW = out + 2 * MAX_PAIRS;
    float* __restrict__ outV = out + 3 * MAX_PAIRS;

    for (int cb = 0; cb < cnt; cb += CHUNK) {
        const int ce = (cb + CHUNK < cnt) ? (cb + CHUNK) : cnt;
        // extract this lane's bits whose global rank falls in [cb, ce)
        if (rb < ce && rb + myc > cb) {
            int r = rb;
            #pragma unroll
            for (int t = 0; t < 8; t++) {
                if (r >= ce) break;
                unsigned word = mask[lane * 8 + t];
                const int pc = __popc(word);
                if (r + pc <= cb) { r += pc; continue; }
                const int jbase = (lane * 8 + t) * 32;
                while (word && r < ce) {
                    const int bpos = __ffs(word) - 1;
                    word &= word - 1;
                    if (r >= cb) jl[r - cb] = jbase + bpos;
                    r++;
                }
            }
        }
        __syncwarp();
        // balanced consumption: single float4 gather per pair
        const int m = ce - cb;
        for (int h = lane; h < m; h += 32) {
            const int j = jl[h];
            const int p = rowoff + cb + h;
            const float4 pj = g_posq[j];
            const float dx = pix - pj.x;
            const float dy = piy - pj.y;
            const float dz = piz - pj.z;
            const float d2 = d2_exact(dx, dy, dz);
            if (p < MAX_PAIRS) {
                outI[p] = fi;
                outJ[p] = (float)j;
                outW[p] = sqrtf(d2);
                outV[3 * p + 0] = dx;
                outV[3 * p + 1] = dy;
                outV[3 * p + 2] = dz;
            }
        }
        __syncwarp();
    }

    // ---- tail phase: forward-poll the final prefix (safe: co-resident grid)
    if (threadIdx.x == 0) {
        unsigned v;
        do { v = *(volatile unsigned*)&g_state[NBLK - 1]; }
        while ((v >> 30) != 2u);
        stotal = (int)(v & 0x3FFFFFFFu);
    }
    __syncthreads();
    int total = stotal;
    if (total > MAX_PAIRS) total = MAX_PAIRS;

    // restore g_cell_cnt for the next replay (all evals finished by now)
    if (b == 0) {
        for (int k = threadIdx.x; k < NCELLS; k += NTHR) g_cell_cnt[k] = 0;
    }

    // fill invalid tail [total, MAX_PAIRS): index=-1, weight=0, vec=0
    for (int q = total + b * NTHR + threadIdx.x; q < MAX_PAIRS; q += NBLK * NTHR) {
        outI[q] = -1.0f;
        outJ[q] = -1.0f;
        outW[q] = 0.0f;
        outV[3 * q + 0] = 0.0f;
        outV[3 * q + 1] = 0.0f;
        outV[3 * q + 2] = 0.0f;
    }
}

// ---------------------------------------------------------------------------
extern "C" void kernel_launch(void* const* d_in, const int* in_sizes, int n_in,
                              void* d_out, int out_size) {
    const float* pos   = (const float*)d_in[0];   // [8192, 3] f32
    const int*   batch = (const int*)d_in[1];     // [8192] i32
    float* out = (float*)d_out;                   // 6 * MAX_PAIRS floats

    (void)in_sizes; (void)n_in; (void)out_size;

    build_kernel<<<NATOMS / 64, 64>>>(pos, batch);
    pairs_kernel<<<NBLK, NTHR>>>(pos, batch, out);
}